// round 15
// baseline (speedup 1.0000x reference)
#include <cuda_runtime.h>
#include <cstdint>

// Problem constants
constexpr int B = 8;
constexpr int S = 4096;
constexpr int D = 2048;
constexpr int E = 64;

// Persistent-kernel layout
constexpr int THR  = 256;
constexpr int GRID = 148 * 4;             // 592 blocks, co-resident at __launch_bounds__(256,4)

// Warp-level stealing chunks: 32 rows x 128 cols (512 B/row per warp, coalesced)
constexpr int COLT      = D / 128;        // 16 column tiles
constexpr int RB_PER_B  = S / 32;         // 128 row-blocks per batch
constexpr int NCHUNKS   = B * RB_PER_B * COLT;   // 16384

constexpr int FOLD_BLOCKS   = 32;         // blocks [0,32): fold phase
constexpr int EXPERT_BLOCKS = E;          // blocks [32,96): one expert each

// Static scratch (allocation-free rule)
__device__ float g_partial[(size_t)NCHUNKS * 128];  // 8 MB, 128 floats per chunk
__device__ float g_mean[B * D];                     // 64 KB
__device__ float g_logits[B * E];                   // 2 KB
__device__ int   g_work;                            // warp chunk ticket (zero-init; reset at end)
__device__ int   g_c0;                              // phase-1 block arrivals
__device__ int   g_c1;                              // fold arrivals
__device__ int   g_c2;                              // gemv ticket

// ---------------------------------------------------------------------------
// ONE persistent kernel with WARP-AUTONOMOUS work stealing (no barriers in
// the steal loop):
//  Phase 1 (all 4736 warps): steal 32x128 chunks via g_work; lane 0 prefetches
//    the next ticket before processing the current chunk, so the atomic's
//    latency is fully hidden. Partial for chunk c -> g_partial[c] (content is
//    chunk-determined -> deterministic regardless of which warp computed it).
//  Phase 2 (blocks 0..31): spin g_c0==592, fold 128 row-block partials per
//    (b, col) position -> g_mean (fixed ascending order).
//  Phase 3 (blocks 32..95 = expert e): stage W[e] to smem (overlaps others'
//    streaming/fold), spin g_c1==32, warp b computes dot(mean[b], W[e]).
//  Phase 4: ticket-last expert block: top-2 (strict > = lowest-index
//    tie-break, matches jax.lax.top_k) + 2-way softmax, counter reset.
// Output: out[0..15] = weights[B][2], out[16..31] = (float)indices[B][2].
// ---------------------------------------------------------------------------
__global__ __launch_bounds__(THR, 4) void fused_kernel(const float* __restrict__ x,
                                                       const float* __restrict__ W,
                                                       const float* __restrict__ bias,
                                                       float* __restrict__ out) {
    int bid  = blockIdx.x;
    int tid  = threadIdx.x;
    int lane = tid & 31;

    __shared__ float4 wsm[D / 4];          // 8 KB (expert blocks)
    __shared__ float  s_logits[B * E];     // 2 KB (ticket block)
    __shared__ int    s_ticket;

    // ---------------- Phase 1: warp-autonomous chunk stealing ----------------
    {
        int nc;
        if (lane == 0) nc = atomicAdd(&g_work, 1);
        int c = __shfl_sync(0xffffffffu, nc, 0);
        while (c < NCHUNKS) {
            if (lane == 0) nc = atomicAdd(&g_work, 1);   // prefetch next ticket

            int rb  = c >> 4;                 // row-block 0..1023
            int ct  = c & (COLT - 1);         // column tile 0..15
            int b   = rb >> 7;                // batch
            int sub = rb & (RB_PER_B - 1);    // row-block within batch
            const float4* __restrict__ xp =
                (const float4*)(x + ((size_t)b * S + (size_t)sub * 32) * D
                                  + ct * 128 + lane * 4);
            float4 acc = make_float4(0.f, 0.f, 0.f, 0.f);
#pragma unroll 8
            for (int s = 0; s < 32; s++) {
                float4 v = __ldcs(xp + (size_t)s * (D / 4));
                acc.x += v.x; acc.y += v.y; acc.z += v.z; acc.w += v.w;
            }
            *(float4*)(g_partial + (size_t)c * 128 + lane * 4) = acc;

            c = __shfl_sync(0xffffffffu, nc, 0);  // atomic long since complete
        }
    }
    __syncthreads();                          // all 8 warps of this block done
    if (tid == 0) {
        __threadfence();                      // release partial writes
        atomicAdd(&g_c0, 1);
    }

    if (bid >= FOLD_BLOCKS + EXPERT_BLOCKS) return;   // blocks 96..591 done

    if (bid < FOLD_BLOCKS) {
        // ---------------- Phase 2: fold -> g_mean ----------------
        if (tid == 0) {
            while (*(volatile int*)&g_c0 != GRID) __nanosleep(32);
            __threadfence();                  // acquire all partials
        }
        __syncthreads();

        int idx = bid * THR + tid;            // float2 position over B*D: 0..8191
        int b   = idx >> 10;                  // 1024 float2 per batch
        int c2  = idx & 1023;
        int col = c2 * 2;
        int ct  = col >> 7;                   // column tile
        int j   = col & 127;                  // offset within tile
        // chunk for (b, rr, ct) = ((b*128 + rr) << 4) + ct ; 128 floats each
        const float* base = g_partial + (((size_t)(b * RB_PER_B) << 4) + ct) * 128 + j;
        float ax = 0.f, ay = 0.f;
#pragma unroll 16
        for (int rr = 0; rr < RB_PER_B; rr++) {     // stride = 16 chunks = 2048 floats
            float2 v = *(const float2*)(base + (size_t)rr * (COLT * 128));
            ax += v.x; ay += v.y;
        }
        const float inv = 1.0f / (float)S;
        *(float2*)(g_mean + (size_t)b * D + col) = make_float2(ax * inv, ay * inv);

        __syncthreads();
        if (tid == 0) {
            __threadfence();                  // release mean writes
            atomicAdd(&g_c1, 1);
        }
        return;
    }

    // ---------------- Phase 3: expert block (GEMV) ----------------
    int e  = bid - FOLD_BLOCKS;               // 0..63
    int bb = tid >> 5;                        // warp = batch 0..7

    // Stage W[e] into smem — overlaps with remaining streaming / fold work
    {
        const float4* __restrict__ wp = (const float4*)(W + (size_t)e * D);
#pragma unroll
        for (int i = tid; i < D / 4; i += THR) wsm[i] = wp[i];
    }

    if (tid == 0) {
        while (*(volatile int*)&g_c1 != FOLD_BLOCKS) __nanosleep(32);
        __threadfence();                      // acquire g_mean
    }
    __syncthreads();

    {
        const float4* __restrict__ xp = (const float4*)(g_mean + (size_t)bb * D);
        float sum = 0.f;
#pragma unroll
        for (int i = 0; i < (D / 4) / 32; i++) {     // 16 float4 per lane
            int idx   = lane + i * 32;
            float4 w4 = wsm[idx];
            float4 x4 = xp[idx];
            sum += w4.x * x4.x + w4.y * x4.y + w4.z * x4.z + w4.w * x4.w;
        }
#pragma unroll
        for (int o = 16; o > 0; o >>= 1) sum += __shfl_xor_sync(0xffffffffu, sum, o);
        if (lane == 0) g_logits[bb * E + e] = sum + bias[e];
    }
    __syncthreads();

    // ---------------- Phase 4: ticket -> top-2 + softmax ----------------
    if (tid == 0) {
        __threadfence();                      // release this block's logits
        int t = atomicAdd(&g_c2, 1);
        if (t == EXPERT_BLOCKS - 1) __threadfence();  // acquire all logits
        s_ticket = t;
    }
    __syncthreads();

    if (s_ticket == EXPERT_BLOCKS - 1) {
        for (int i = tid; i < B * E; i += THR) s_logits[i] = g_logits[i];
        __syncthreads();

        if (tid < B) {
            const float* lg = s_logits + tid * E;
            float v1 = -1e30f, v2 = -1e30f;
            int   i1 = 0, i2 = 0;
#pragma unroll
            for (int k = 0; k < E; k++) {
                float v = lg[k];
                if (v > v1) { v2 = v1; i2 = i1; v1 = v; i1 = k; }
                else if (v > v2) { v2 = v; i2 = k; }
            }
            float e2 = __expf(v2 - v1);       // stable 2-way softmax
            float denom = 1.0f + e2;
            out[tid * 2 + 0]      = 1.0f / denom;
            out[tid * 2 + 1]      = e2 / denom;
            out[16 + tid * 2 + 0] = (float)i1;
            out[16 + tid * 2 + 1] = (float)i2;
        }
        __syncthreads();
        if (tid == 0) {                       // reset for next graph replay;
            __threadfence();                  // all counter users have passed by now
            g_work = 0;
            g_c0 = 0;
            g_c1 = 0;
            g_c2 = 0;
        }
    }
}

extern "C" void kernel_launch(void* const* d_in, const int* in_sizes, int n_in,
                              void* d_out, int out_size) {
    const float* x    = (const float*)d_in[0];  // [B, S, D] fp32
    const float* W    = (const float*)d_in[1];  // [E, D]   fp32
    const float* bias = (const float*)d_in[2];  // [E]      fp32
    float* out        = (float*)d_out;          // 32 floats: weights then indices

    fused_kernel<<<GRID, THR>>>(x, W, bias, out);
}

// round 16
// speedup vs baseline: 1.0189x; 1.0189x over previous
#include <cuda_runtime.h>
#include <cstdint>

// Problem constants
constexpr int B = 8;
constexpr int S = 4096;
constexpr int D = 2048;
constexpr int E = 64;

// Streaming tiling — EXACT R2 shape (measured 38 us): grid 2048, 3.5 waves
constexpr int SCHUNKS = 128;            // partial-sum chunks over S
constexpr int SPC     = S / SCHUNKS;    // 32 rows per chunk
constexpr int DTILES  = 2;              // 2048 d -> 2 tiles of 1024 (256 thr * float4)
constexpr int THR     = 256;
constexpr int GRID    = SCHUNKS * B * DTILES;   // 2048 blocks

// Tail roles assigned by FINISH TICKET (last finishers -> shortest spins)
constexpr int FOLD_BLOCKS   = 32;
constexpr int EXPERT_BLOCKS = E;                       // 64
constexpr int EXPERT_T0     = GRID - FOLD_BLOCKS - EXPERT_BLOCKS;  // 1952
constexpr int FOLD_T0       = GRID - FOLD_BLOCKS;                  // 2016

// Static scratch (allocation-free rule)
__device__ float g_partial[(size_t)SCHUNKS * B * D];  // 8 MB (L2-resident, 126MB L2)
__device__ float g_mean[B * D];                       // 64 KB
__device__ float g_logits[B * E];                     // 2 KB
__device__ int   g_c0;   // finish tickets (zero-init; reset at end of each run)
__device__ int   g_c1;   // fold arrivals
__device__ int   g_c2;   // gemv ticket

// ---------------------------------------------------------------------------
// ONE kernel, grid=2048 (multi-wave: HW scheduler load-balances streaming —
// the measured-fastest config). Every block:
//   1) streams its 32-row x 1024-col chunk -> g_partial (R2-identical),
//   2) takes a finish ticket t.
//      t <  1952 : exit (frees the SM for later waves)
//      t in [1952,2016): expert role e=t-1952 — prefetch W[e] to smem,
//                        spin g_c1==32, warp b computes dot(mean[b], W[e])
//      t in [2016,2048): fold role (these are the LAST 32 finishers, so the
//                        g_c0==2048 spin is sub-us) — fold 128 partials per
//                        position -> g_mean, fixed ascending order
//   3) last g_c2 ticket: top-2 (strict > = lowest-index tie-break, matching
//      jax.lax.top_k) + 2-way softmax, then counter reset for graph replays.
// Role->work mapping is keyed to ticket VALUE, and all float reductions have
// fixed order -> output bit-deterministic regardless of scheduling.
// Output: out[0..15] = weights[B][2], out[16..31] = (float)indices[B][2].
// ---------------------------------------------------------------------------
__global__ __launch_bounds__(THR) void fused_kernel(const float* __restrict__ x,
                                                    const float* __restrict__ W,
                                                    const float* __restrict__ bias,
                                                    float* __restrict__ out) {
    int bid = blockIdx.x;
    int tid = threadIdx.x;

    __shared__ int    s_t;
    __shared__ float4 wsm[D / 4];          // 8 KB (expert role)
    __shared__ float  s_logits[B * E];     // 2 KB (top-2 block)
    __shared__ int    s_ticket;

    // ---------------- Phase 1: streaming partial sums (R2-identical) ----------------
    {
        int chunk = bid / (B * DTILES);
        int rem   = bid % (B * DTILES);
        int b     = rem / DTILES;
        int dt    = rem % DTILES;
        int d     = dt * (THR * 4) + tid * 4;

        const float4* __restrict__ xp =
            (const float4*)(x + ((size_t)b * S + (size_t)chunk * SPC) * D + d);
        float4 acc = make_float4(0.f, 0.f, 0.f, 0.f);
#pragma unroll 8
        for (int s = 0; s < SPC; s++) {
            float4 v = xp[(size_t)s * (D / 4)];
            acc.x += v.x; acc.y += v.y; acc.z += v.z; acc.w += v.w;
        }
        *(float4*)(g_partial + (size_t)chunk * (B * D) + (size_t)b * D + d) = acc;
    }
    __syncthreads();
    if (tid == 0) {
        __threadfence();                    // release partial writes
        s_t = atomicAdd(&g_c0, 1);          // finish ticket
    }
    __syncthreads();
    int t = s_t;

    if (t < EXPERT_T0) return;              // most blocks: done, free the SM

    if (t >= FOLD_T0) {
        // ---------------- Fold role (last 32 finishers) ----------------
        if (tid == 0) {
            while (*(volatile int*)&g_c0 != GRID) __nanosleep(32);   // sub-us: <=31 behind
            __threadfence();                // acquire all partials
        }
        __syncthreads();

        int fb  = t - FOLD_T0;              // 0..31
        int idx = fb * THR + tid;           // float2 position over B*D: 0..8191
        const float* base = g_partial + (size_t)idx * 2;
        float ax = 0.f, ay = 0.f;
#pragma unroll 16
        for (int c = 0; c < SCHUNKS; c++) { // fixed ascending order
            float2 v = *(const float2*)(base + (size_t)c * (B * D));
            ax += v.x; ay += v.y;
        }
        const float inv = 1.0f / (float)S;
        *(float2*)(g_mean + (size_t)idx * 2) = make_float2(ax * inv, ay * inv);

        __syncthreads();
        if (tid == 0) {
            __threadfence();                // release mean writes
            atomicAdd(&g_c1, 1);
        }
        return;
    }

    // ---------------- Expert role ----------------
    int e    = t - EXPERT_T0;               // 0..63
    int lane = tid & 31;
    int bb   = tid >> 5;                    // warp = batch 0..7

    // Prefetch W[e] into smem — overlaps with straggler streaming + fold
    {
        const float4* __restrict__ wp = (const float4*)(W + (size_t)e * D);
#pragma unroll
        for (int i = tid; i < D / 4; i += THR) wsm[i] = wp[i];
    }

    if (tid == 0) {
        while (*(volatile int*)&g_c1 != FOLD_BLOCKS) __nanosleep(32);
        __threadfence();                    // acquire g_mean
    }
    __syncthreads();

    {
        const float4* __restrict__ xp = (const float4*)(g_mean + (size_t)bb * D);
        float sum = 0.f;
#pragma unroll
        for (int i = 0; i < (D / 4) / 32; i++) {   // 16 float4 per lane
            int idx   = lane + i * 32;
            float4 w4 = wsm[idx];
            float4 x4 = xp[idx];
            sum += w4.x * x4.x + w4.y * x4.y + w4.z * x4.z + w4.w * x4.w;
        }
#pragma unroll
        for (int o = 16; o > 0; o >>= 1) sum += __shfl_xor_sync(0xffffffffu, sum, o);
        if (lane == 0) g_logits[bb * E + e] = sum + bias[e];
    }
    __syncthreads();

    // ---------------- Final: ticket -> top-2 + softmax ----------------
    if (tid == 0) {
        __threadfence();                    // release this block's logits
        int tk = atomicAdd(&g_c2, 1);
        if (tk == EXPERT_BLOCKS - 1) __threadfence();  // acquire all logits
        s_ticket = tk;
    }
    __syncthreads();

    if (s_ticket == EXPERT_BLOCKS - 1) {
        for (int i = tid; i < B * E; i += THR) s_logits[i] = g_logits[i];
        __syncthreads();

        if (tid < B) {
            const float* lg = s_logits + tid * E;
            float v1 = -1e30f, v2 = -1e30f;
            int   i1 = 0, i2 = 0;
#pragma unroll
            for (int k = 0; k < E; k++) {
                float v = lg[k];
                if (v > v1) { v2 = v1; i2 = i1; v1 = v; i1 = k; }
                else if (v > v2) { v2 = v; i2 = k; }
            }
            float e2 = __expf(v2 - v1);     // stable 2-way softmax
            float denom = 1.0f + e2;
            out[tid * 2 + 0]      = 1.0f / denom;
            out[tid * 2 + 1]      = e2 / denom;
            out[16 + tid * 2 + 0] = (float)i1;
            out[16 + tid * 2 + 1] = (float)i2;
        }
        __syncthreads();
        if (tid == 0) {                     // reset for next graph replay;
            __threadfence();                // every counter consumer has passed
            g_c0 = 0;
            g_c1 = 0;
            g_c2 = 0;
        }
    }
}

extern "C" void kernel_launch(void* const* d_in, const int* in_sizes, int n_in,
                              void* d_out, int out_size) {
    const float* x    = (const float*)d_in[0];  // [B, S, D] fp32
    const float* W    = (const float*)d_in[1];  // [E, D]   fp32
    const float* bias = (const float*)d_in[2];  // [E]      fp32
    float* out        = (float*)d_out;          // 32 floats: weights then indices

    fused_kernel<<<GRID, THR>>>(x, W, bias, out);
}